// round 6
// baseline (speedup 1.0000x reference)
#include <cuda_runtime.h>
#include <cuda_bf16.h>

// StixelLoss v6: cp.async-staged pipeline, thread-per-column dense scan.
// inputs:  (B=256, C=2, H=192, W=256) f32 in (1e-4, 1-1e-4)
// targets: (1, B, C, H, W) f32
// out:     scalar f32 = 1.0*bce_mean + 0.001*cuts + 0.1*dense

#define HH   192
#define WW   256
#define NBC  512
#define NCH  48          // chunks of 4 rows
#define NST  5           // pipeline stages

__global__ void sx_zero_kernel(float* out) {
    if (threadIdx.x == 0) out[0] = 0.0f;
}

__device__ __forceinline__ unsigned sm32(const void* p) {
    return (unsigned)__cvta_generic_to_shared(p);
}

__global__ __launch_bounds__(256, 4)
void stixel_kernel(const float* __restrict__ inp,
                   const float* __restrict__ tgt,
                   float* __restrict__ out) {
    __shared__ float sp [NST][4][WW];   // staged inputs
    __shared__ float stg[NST][4][WW];   // staged targets
    __shared__ float sred[8];

    const int bc  = blockIdx.x;      // b*2 + c
    const int c   = bc & 1;
    const int col = threadIdx.x;     // 0..255 = column

    const float* gp = inp + (size_t)bc * (HH * WW);
    const float* gt = tgt + (size_t)bc * (HH * WW);

    // ---- prologue: prefetch chunks 0..NST-2 into stages 0..NST-2 ----
    #pragma unroll
    for (int j = 0; j < NST - 1; ++j) {
        unsigned dp = sm32(&sp [j][0][0]) + col * 16;
        unsigned dt = sm32(&stg[j][0][0]) + col * 16;
        const float* srcp = gp + j * 1024 + col * 4;   // 4 rows = 1024 floats
        const float* srct = gt + j * 1024 + col * 4;
        asm volatile("cp.async.cg.shared.global [%0], [%1], 16;\n" :: "r"(dp), "l"(srcp) : "memory");
        asm volatile("cp.async.cg.shared.global [%0], [%1], 16;\n" :: "r"(dt), "l"(srct) : "memory");
        asm volatile("cp.async.commit_group;\n" ::: "memory");
    }

    float bce0 = 0.0f, bce1 = 0.0f;
    float dense = 0.0f;
    int   cuts  = 0;
    int   prev  = -1;          // -1 = no visible predecessor
    int   st_c  = 0;           // consume stage
    int   st_p  = NST - 1;     // produce stage
    int   ch_p  = NST - 1;     // next chunk to produce

    for (int w = 0; w < 6; ++w) {          // 6 mask words x 32 rows
        unsigned curw = 0;
        #pragma unroll
        for (int k = 0; k < 8; ++k) {      // 8 chunks per word
            asm volatile("cp.async.wait_group 3;\n" ::: "memory");
            __syncthreads();

            // consume 4 rows from stage st_c
            #pragma unroll
            for (int i = 0; i < 4; ++i) {
                float p = sp [st_c][i][col];
                float t = stg[st_c][i][col];
                float lp  = __log2f(p);
                float l1p = __log2f(1.0f - p);
                float term = l1p + t * (lp - l1p);
                if (i & 1) bce1 += term; else bce0 += term;
                if (p > 0.5f) curw |= (1u << (k * 4 + i));
            }

            // produce chunk ch_p into stage st_p (empty group past the end)
            if (ch_p < NCH) {
                unsigned dp = sm32(&sp [st_p][0][0]) + col * 16;
                unsigned dt = sm32(&stg[st_p][0][0]) + col * 16;
                const float* srcp = gp + ch_p * 1024 + col * 4;
                const float* srct = gt + ch_p * 1024 + col * 4;
                asm volatile("cp.async.cg.shared.global [%0], [%1], 16;\n" :: "r"(dp), "l"(srcp) : "memory");
                asm volatile("cp.async.cg.shared.global [%0], [%1], 16;\n" :: "r"(dt), "l"(srct) : "memory");
            }
            asm volatile("cp.async.commit_group;\n" ::: "memory");
            ch_p++;
            st_p = (st_p == NST - 1) ? 0 : st_p + 1;
            st_c = (st_c == NST - 1) ? 0 : st_c + 1;
        }

        if (c == 0) {
            // cuts: all 192 rows of channel 0 count
            cuts += __popc(curw);
        } else {
            // dense scan of this word. Reference semantics:
            //  - a hit at h=0 is invisible (prev!=0 gate)   -> clear bit 0
            //  - h=191 is excluded (loop runs h<H-1)        -> clear bit 31 of word 5
            unsigned wb = curw;
            if (w == 0) wb &= ~1u;
            if (w == 5) wb &= 0x7fffffffu;
            const int base = w * 32;
            while (wb) {
                int b = __ffs(wb) - 1;
                wb &= (wb - 1);
                int pos = base + b;
                if (prev >= 0) {
                    float d = (float)(pos - prev);
                    dense += __fdividef(1.0f, d * d * d);
                }
                prev = pos;
            }
        }
    }

    // combine (ALPHA=1, BETA=0.001, GAMMA=0.1); bce is in log2 units
    const float SCALE_BCE = -0.69314718055994531f /
                            (float)((size_t)NBC * HH * WW);
    float val = (bce0 + bce1) * SCALE_BCE + 0.001f * (float)cuts + 0.1f * dense;

    // block reduction over 256 threads
    #pragma unroll
    for (int off = 16; off > 0; off >>= 1)
        val += __shfl_down_sync(0xffffffffu, val, off);
    int lane = threadIdx.x & 31;
    int wid  = threadIdx.x >> 5;
    if (lane == 0) sred[wid] = val;
    __syncthreads();
    if (wid == 0) {
        val = (lane < 8) ? sred[lane] : 0.0f;
        #pragma unroll
        for (int off = 4; off > 0; off >>= 1)
            val += __shfl_down_sync(0xffffffffu, val, off);
        if (lane == 0) atomicAdd(out, val);
    }
}

extern "C" void kernel_launch(void* const* d_in, const int* in_sizes, int n_in,
                              void* d_out, int out_size) {
    const float* inp = (const float*)d_in[0];
    const float* tgt = (const float*)d_in[1];
    float* out = (float*)d_out;

    sx_zero_kernel<<<1, 32>>>(out);
    stixel_kernel<<<NBC, 256>>>(inp, tgt, out);
}